// round 16
// baseline (speedup 1.0000x reference)
#include <cuda_runtime.h>
#include <cuda_fp16.h>
#include <cuda_bf16.h>
#include <cstdint>

#define B_    8
#define N_    256
#define C_    512
#define HW_   64
#define DIM_  1024
#define M_    (B_ * N_)          // 2048

// ---------------- device scratch (no allocation allowed) -------------------
__device__ __half g_zh[M_ * DIM_];     // unscaled projections, fp16 (4 MB)
__device__ __half g_fcwh[DIM_ * DIM_]; // fp16 copy of fc_w (2 MB)
__device__ float  g_msum[2 * M_];      // per-(b,n) partial sums (2 c-halves)
__device__ float  g_s[M_];             // a1*a2*a3 per (b,n)
__device__ float  g_cvec[DIM_];        // bs_vec @ fc_w^T + fc_b (fp32)

// ---------------- PTX helpers (all sm_80-era: safe on compute_103) ---------
#define CP_ASYNC16(dst_u32, src_ptr) \
    asm volatile("cp.async.cg.shared.global [%0], [%1], 16;\n" \
                 :: "r"(dst_u32), "l"(src_ptr))
#define CP_COMMIT()  asm volatile("cp.async.commit_group;\n" ::)
#define CP_WAIT2()   asm volatile("cp.async.wait_group 2;\n" ::)

#define LDSM_X4(r, addr) \
    asm volatile("ldmatrix.sync.aligned.m8n8.x4.shared.b16 {%0,%1,%2,%3}, [%4];" \
        : "=r"((r)[0]), "=r"((r)[1]), "=r"((r)[2]), "=r"((r)[3]) : "r"(addr))

#define MMA_F16(d, a, b0v, b1v) \
    asm volatile("mma.sync.aligned.m16n8k16.row.col.f32.f16.f16.f32 " \
        "{%0,%1,%2,%3}, {%4,%5,%6,%7}, {%8,%9}, {%0,%1,%2,%3};" \
        : "+f"((d)[0]), "+f"((d)[1]), "+f"((d)[2]), "+f"((d)[3]) \
        : "r"((a)[0]), "r"((a)[1]), "r"((a)[2]), "r"((a)[3]), \
          "r"(b0v), "r"(b1v))

// ===========================================================================
// K1: single fused pass over x (256 MB, read exactly once).
// 8 lanes per channel (lane sub owns bytes [sub*16] and [128+sub*16] of the
// 256B channel slab -> warp LDG = 4 channels x 1 line = fully coalesced).
// 3-stage shuffle reduce (vs 4), NT=8 m per block with 8 loads in flight,
// channel dim split over gridDim.y=2 (halves Ws L2 re-reads).
// ===========================================================================
__global__ __launch_bounds__(256)
void k_reduce(const float4* __restrict__ x4, const float4* __restrict__ Ws4)
{
    const int m0    = blockIdx.x * 8;
    const int chalf = blockIdx.y;          // 0/1 -> channels [chalf*256, +256)
    const int tid   = threadIdx.x;
    const int warp  = tid >> 5;
    const int lane  = tid & 31;
    const int cl    = lane >> 3;           // channel within warp (0..3)
    const int sub   = lane & 7;            // lane within 8-lane channel group

    float acc[8];
    #pragma unroll
    for (int j = 0; j < 8; ++j) acc[j] = 0.f;

    #pragma unroll 1
    for (int it = 0; it < 8; ++it) {
        const int c = chalf * 256 + it * 32 + warp * 4 + cl;
        // Ws: [c][o][64] floats -> float4 idx c*32 + o*16 + q
        const float4 w00 = Ws4[c * 32 + sub];
        const float4 w01 = Ws4[c * 32 + 8 + sub];
        const float4 w10 = Ws4[c * 32 + 16 + sub];
        const float4 w11 = Ws4[c * 32 + 24 + sub];

        #pragma unroll
        for (int mb = 0; mb < 2; ++mb) {
            float4 xa[4][2];               // 8 independent loads in flight
            #pragma unroll
            for (int i = 0; i < 4; ++i) {
                const int base = ((m0 + mb * 4 + i) * C_ + c) * 16;
                xa[i][0] = x4[base + sub];
                xa[i][1] = x4[base + 8 + sub];
            }
            #pragma unroll
            for (int i = 0; i < 4; ++i) {
                const float4 a0 = xa[i][0], a1 = xa[i][1];
                float z0 = a0.x * w00.x + a0.y * w00.y + a0.z * w00.z + a0.w * w00.w
                         + a1.x * w01.x + a1.y * w01.y + a1.z * w01.z + a1.w * w01.w;
                float z1 = a0.x * w10.x + a0.y * w10.y + a0.z * w10.z + a0.w * w10.w
                         + a1.x * w11.x + a1.y * w11.y + a1.z * w11.z + a1.w * w11.w;
                acc[mb * 4 + i] += (a0.x + a0.y) + (a0.z + a0.w)
                                 + (a1.x + a1.y) + (a1.z + a1.w);
                #pragma unroll
                for (int off = 4; off; off >>= 1) {   // stays in 8-lane group
                    z0 += __shfl_xor_sync(0xffffffffu, z0, off);
                    z1 += __shfl_xor_sync(0xffffffffu, z1, off);
                }
                if (sub == 0) {
                    *(__half2*)&g_zh[(m0 + mb * 4 + i) * DIM_ + 2 * c] =
                        __floats2half2_rn(z0, z1);
                }
            }
        }
    }

    // deterministic block reduction of 8 per-m partials (this c-half)
    #pragma unroll
    for (int j = 0; j < 8; ++j)
        #pragma unroll
        for (int off = 16; off; off >>= 1)
            acc[j] += __shfl_xor_sync(0xffffffffu, acc[j], off);
    __shared__ float red[8][8];
    if (lane == 0) {
        #pragma unroll
        for (int j = 0; j < 8; ++j) red[warp][j] = acc[j];
    }
    __syncthreads();
    if (tid < 8) {
        float t = 0.f;
        #pragma unroll
        for (int w = 0; w < 8; ++w) t += red[w][tid];
        g_msum[chalf * M_ + m0 + tid] = t;
    }
}

// ===========================================================================
// K2: attention chain on the 2048-element mean vector. One block per b.
// ===========================================================================
__global__ __launch_bounds__(256)
void k_att(const float* __restrict__ conv_w, const float* __restrict__ conv_b)
{
    const int b = blockIdx.x;
    const int n = threadIdx.x;
    __shared__ float sm_m[N_];
    sm_m[n] = (g_msum[b * N_ + n] + g_msum[M_ + b * N_ + n]) * (1.0f / 32768.0f);
    float stot = 1.f;
    #pragma unroll
    for (int i = 0; i < 3; ++i) {
        __syncthreads();
        float acc = conv_b[i];
        #pragma unroll
        for (int j = 0; j < 5; ++j) {
            const int idx = n + j - 2;
            const float v = (idx >= 0 && idx < N_) ? sm_m[idx] : 0.f;
            acc += v * conv_w[i * 5 + j];
        }
        const float att = 1.0f / (1.0f + __expf(-acc));
        stot *= att;
        __syncthreads();
        sm_m[n] *= att;
    }
    g_s[b * N_ + n] = stot;
}

// ===========================================================================
// K3: cvec[d] = bs_vec @ fc_w[d,:] + fc_b[d] (fp32); fp16 copy of fc_w.
// ===========================================================================
__global__ __launch_bounds__(256)
void k_cvec(const float* __restrict__ bs, const float* __restrict__ fc_w,
            const float* __restrict__ fc_b)
{
    const int gw   = (blockIdx.x * blockDim.x + threadIdx.x) >> 5;
    const int lane = threadIdx.x & 31;
    float acc = 0.f;
    for (int k = lane; k < DIM_; k += 32) {
        const float v = fc_w[gw * DIM_ + k];
        acc += bs[k] * v;
        g_fcwh[gw * DIM_ + k] = __float2half_rn(v);
    }
    #pragma unroll
    for (int off = 16; off; off >>= 1)
        acc += __shfl_xor_sync(0xffffffffu, acc, off);
    if (lane == 0) g_cvec[gw] = acc + fc_b[gw];
}

// ===========================================================================
// K4: out[m,d] = s[m]*(z @ fcw^T)[m,d] + cvec[d]   (unchanged from R15)
// fp16 mma.m16n8k16 + ldmatrix. CTA 128x128, BK=64 fp16, 4-stage cp.async,
// 512 threads = 16 warps (4x4, warp tile 32x32).
// ===========================================================================
#define GBM      128
#define GBN      128
#define GBK      64
#define NCHUNK   (DIM_ / GBK)           // 16
#define GSTAGES  4
#define STG_B    (GBM * 128)            // 16384 bytes per operand stage
#define SMEM_GEMM (2 * GSTAGES * STG_B) // 131072 B

__device__ __forceinline__ uint32_t swz(int row, int kg) {
    return (uint32_t)(row * 128 + ((kg ^ (row & 7)) << 4));
}

__global__ __launch_bounds__(512)
void k_gemm_mma(float* __restrict__ out)
{
    extern __shared__ __align__(128) char smc[];
    const uint32_t smem_base = (uint32_t)__cvta_generic_to_shared(smc);

    const int tid  = threadIdx.x;
    const int warp = tid >> 5;
    const int lane = tid & 31;
    const int wm   = warp >> 2;
    const int wn   = warp & 3;
    const int m_cta = blockIdx.y * GBM;
    const int n_cta = blockIdx.x * GBN;

    const int lrow = tid >> 2;
    const int lkg0 = (tid & 3) * 2;
    const __half* srcA = &g_zh[(m_cta + lrow) * DIM_];
    const __half* srcB = &g_fcwh[(n_cta + lrow) * DIM_];
    uint32_t dstA[2], dstB[2];
    #pragma unroll
    for (int g = 0; g < 2; ++g) {
        dstA[g] = smem_base + swz(lrow, lkg0 + g);
        dstB[g] = smem_base + GSTAGES * STG_B + swz(lrow, lkg0 + g);
    }

    const int a_row = wm * 32 + (lane & 7) + ((lane >> 3) & 1) * 8;
    const int a_kgl = (lane >> 4);
    const int b_row = wn * 32 + (lane & 7) + ((lane >> 4) & 1) * 8;
    const int b_kgl = (lane >> 3) & 1;

    float acc[2][4][4];
    #pragma unroll
    for (int i = 0; i < 2; ++i)
        #pragma unroll
        for (int j = 0; j < 4; ++j)
            #pragma unroll
            for (int e = 0; e < 4; ++e) acc[i][j][e] = 0.f;

    #pragma unroll
    for (int t = 0; t < GSTAGES - 1; ++t) {
        const int k0 = t * GBK;
        #pragma unroll
        for (int g = 0; g < 2; ++g) {
            CP_ASYNC16(dstA[g] + t * STG_B, srcA + k0 + (lkg0 + g) * 8);
            CP_ASYNC16(dstB[g] + t * STG_B, srcB + k0 + (lkg0 + g) * 8);
        }
        CP_COMMIT();
    }

    #pragma unroll 1
    for (int t = 0; t < NCHUNK; ++t) {
        CP_WAIT2();
        __syncthreads();

        const int u = t + GSTAGES - 1;
        if (u < NCHUNK) {
            const int s2 = (u & (GSTAGES - 1)) * STG_B;
            const int k0 = u * GBK;
            #pragma unroll
            for (int g = 0; g < 2; ++g) {
                CP_ASYNC16(dstA[g] + s2, srcA + k0 + (lkg0 + g) * 8);
                CP_ASYNC16(dstB[g] + s2, srcB + k0 + (lkg0 + g) * 8);
            }
        }
        CP_COMMIT();

        const uint32_t aS = smem_base + (t & (GSTAGES - 1)) * STG_B;
        const uint32_t bS = aS + GSTAGES * STG_B;

        uint32_t aF[2][2][4], bF[2][2][4];
        #pragma unroll
        for (int mt = 0; mt < 2; ++mt)
            LDSM_X4(aF[0][mt], aS + swz(a_row + mt * 16, a_kgl));
        #pragma unroll
        for (int bt = 0; bt < 2; ++bt)
            LDSM_X4(bF[0][bt], bS + swz(b_row + bt * 16, b_kgl));

        #pragma unroll
        for (int kk = 0; kk < 4; ++kk) {
            const int cur = kk & 1, nxt = cur ^ 1;
            if (kk < 3) {
                const int kg = (kk + 1) * 2;
                #pragma unroll
                for (int mt = 0; mt < 2; ++mt)
                    LDSM_X4(aF[nxt][mt], aS + swz(a_row + mt * 16, kg + a_kgl));
                #pragma unroll
                for (int bt = 0; bt < 2; ++bt)
                    LDSM_X4(bF[nxt][bt], bS + swz(b_row + bt * 16, kg + b_kgl));
            }
            #pragma unroll
            for (int mt = 0; mt < 2; ++mt) {
                MMA_F16(acc[mt][0], aF[cur][mt], bF[cur][0][0], bF[cur][0][1]);
                MMA_F16(acc[mt][1], aF[cur][mt], bF[cur][0][2], bF[cur][0][3]);
                MMA_F16(acc[mt][2], aF[cur][mt], bF[cur][1][0], bF[cur][1][1]);
                MMA_F16(acc[mt][3], aF[cur][mt], bF[cur][1][2], bF[cur][1][3]);
            }
        }
    }

    const int r  = lane >> 2;
    const int c2 = (lane & 3) * 2;
    #pragma unroll
    for (int mt = 0; mt < 2; ++mt) {
        const int row0 = m_cta + wm * 32 + mt * 16 + r;
        const float s0 = g_s[row0];
        const float s1 = g_s[row0 + 8];
        #pragma unroll
        for (int nt = 0; nt < 4; ++nt) {
            const int col = n_cta + wn * 32 + nt * 8 + c2;
            const float2 cv = *(const float2*)&g_cvec[col];
            float2 o0, o1;
            o0.x = s0 * acc[mt][nt][0] + cv.x;
            o0.y = s0 * acc[mt][nt][1] + cv.y;
            o1.x = s1 * acc[mt][nt][2] + cv.x;
            o1.y = s1 * acc[mt][nt][3] + cv.y;
            *(float2*)&out[row0 * DIM_ + col]       = o0;
            *(float2*)&out[(row0 + 8) * DIM_ + col] = o1;
        }
    }
}

// ===========================================================================
extern "C" void kernel_launch(void* const* d_in, const int* in_sizes, int n_in,
                              void* d_out, int out_size)
{
    (void)in_sizes; (void)n_in; (void)out_size;
    const float* x      = (const float*)d_in[0];
    const float* conv_w = (const float*)d_in[1];
    const float* conv_b = (const float*)d_in[2];
    const float* Ws     = (const float*)d_in[3];
    const float* bs     = (const float*)d_in[4];
    const float* fc_w   = (const float*)d_in[5];
    const float* fc_b   = (const float*)d_in[6];
    float* out = (float*)d_out;

    dim3 rg(M_ / 8, 2);                    // 512 blocks
    k_reduce<<<rg, 256>>>((const float4*)x, (const float4*)Ws);
    k_att<<<B_, 256>>>(conv_w, conv_b);
    k_cvec<<<DIM_ / 8, 256>>>(bs, fc_w, fc_b);

    cudaFuncSetAttribute(k_gemm_mma, cudaFuncAttributeMaxDynamicSharedMemorySize,
                         SMEM_GEMM);
    dim3 grid(DIM_ / GBN, M_ / GBM);       // (8, 16) = 128 CTAs, one wave
    k_gemm_mma<<<grid, 512, SMEM_GEMM>>>(out);
}